// round 4
// baseline (speedup 1.0000x reference)
#include <cuda_runtime.h>
#include <cuda_bf16.h>

#define NA 8192
#define NP 65536
#define FDIM 128
#define RD 20
#define NB 5

// Scratch (allocation-free rule: __device__ globals)
__device__ __align__(16) float g_x[NA * 384];
__device__ __align__(16) float g_dq[NA * FDIM];
__device__ __align__(16) float g_dmu[NA * 384];
__device__ __align__(16) float g_desc[NP * 384];   // per-block filter descriptors

__device__ __forceinline__ float silu(float z) { return z / (1.f + __expf(-z)); }

__device__ __forceinline__ void red4(float* p, float a, float b, float c, float d) {
    asm volatile("red.global.add.v4.f32 [%0], {%1,%2,%3,%4};"
                 :: "l"(p), "f"(a), "f"(b), "f"(c), "f"(d) : "memory");
}

// ---------------------------------------------------------------------------
// k_filter: desc[p, 0:384] = (rbf[p] @ fW + fb) * cut[p]   for one block b.
// CTA = 384 threads (12 warps), 32 pairs per CTA. Warp w: slice s=w%3 owns
// 32 float4 columns, octet o=w/3 owns 8 pairs -> fW LDS.128 amortized 8x.
// ---------------------------------------------------------------------------
__global__ void __launch_bounds__(384) k_filter(
    const float* __restrict__ rbf, const float* __restrict__ cut,
    const float* __restrict__ fW,   // pre-offset by b*384, row stride 1920
    const float* __restrict__ fb,   // pre-offset by b*384
    float* __restrict__ desc)
{
    __shared__ __align__(16) float fw_s[RD * 384];
    __shared__ __align__(16) float fb_s[384];
    __shared__ float rbf_s[32][RD];
    __shared__ float cut_s[32];
    const int tid = threadIdx.x;
    const int p0 = blockIdx.x * 32;

    for (int c = tid; c < RD * 384; c += 384) {
        int r = c / 384, cc = c - r * 384;
        fw_s[c] = fW[r * 1920 + cc];
    }
    fb_s[tid] = fb[tid];
    for (int c = tid; c < 32 * RD; c += 384)
        rbf_s[c / RD][c % RD] = rbf[(p0 + c / RD) * RD + (c % RD)];
    if (tid < 32) cut_s[tid] = cut[p0 + tid];
    __syncthreads();

    const int w = tid >> 5, lane = tid & 31;
    const int s = w % 3;
    const int o = w / 3;
    const float4* fw4 = (const float4*)fw_s;     // [RD][96]
    const float4 bv = ((const float4*)fb_s)[s * 32 + lane];

    float4 acc[8];
#pragma unroll
    for (int pp = 0; pp < 8; pp++) acc[pp] = make_float4(0.f, 0.f, 0.f, 0.f);
#pragma unroll
    for (int r = 0; r < RD; r++) {
        float4 wv = fw4[r * 96 + s * 32 + lane];
#pragma unroll
        for (int pp = 0; pp < 8; pp++) {
            float rb = rbf_s[o * 8 + pp][r];
            acc[pp].x += rb * wv.x; acc[pp].y += rb * wv.y;
            acc[pp].z += rb * wv.z; acc[pp].w += rb * wv.w;
        }
    }
    float4* out = (float4*)desc;
#pragma unroll
    for (int pp = 0; pp < 8; pp++) {
        const int p = p0 + o * 8 + pp;
        const float cu = cut_s[o * 8 + pp];
        float4 v;
        v.x = (acc[pp].x + bv.x) * cu; v.y = (acc[pp].y + bv.y) * cu;
        v.z = (acc[pp].z + bv.z) * cu; v.w = (acc[pp].w + bv.w) * cu;
        out[p * 96 + s * 32 + lane] = v;
    }
}

// ---------------------------------------------------------------------------
// k_x: x = silu(q @ W1 + b1) @ W2 + b2.  32 atoms/CTA, 128 threads.
// Microtile 8 atoms x 4 features per thread; atom operand via broadcast LDS
// (vectorized over k by unroll), weights via LDG.128 (L1-hot).
// ---------------------------------------------------------------------------
__global__ void __launch_bounds__(128) k_x(
    const float* __restrict__ q,
    const float* __restrict__ W1, const float* __restrict__ b1,
    const float* __restrict__ W2, const float* __restrict__ b2,
    float* __restrict__ x)
{
    __shared__ __align__(16) float qs[32 * FDIM];
    __shared__ __align__(16) float hs[32 * FDIM];
    const int tid = threadIdx.x;
    const int atom0 = blockIdx.x * 32;
    const int fgrp = tid & 31;          // f0 = fgrp*4
    const int agrp = tid >> 5;          // a0 = agrp*8
    const int f0 = fgrp * 4;
    const int a0 = agrp * 8;

    {
        const float4* src = (const float4*)(q + atom0 * FDIM);
        float4* dst = (float4*)qs;
        for (int c = tid; c < 32 * 32; c += 128) dst[c] = src[c];
    }
    __syncthreads();

    // GEMM1 + silu -> hs
    {
        float acc[8][4];
        const float4 bv = *(const float4*)(b1 + f0);
#pragma unroll
        for (int a = 0; a < 8; a++) {
            acc[a][0] = bv.x; acc[a][1] = bv.y; acc[a][2] = bv.z; acc[a][3] = bv.w;
        }
#pragma unroll 4
        for (int k = 0; k < FDIM; k++) {
            const float4 wv = *(const float4*)(W1 + k * FDIM + f0);
#pragma unroll
            for (int a = 0; a < 8; a++) {
                const float qa = qs[(a0 + a) * FDIM + k];
                acc[a][0] += qa * wv.x; acc[a][1] += qa * wv.y;
                acc[a][2] += qa * wv.z; acc[a][3] += qa * wv.w;
            }
        }
#pragma unroll
        for (int a = 0; a < 8; a++) {
            float4 h;
            h.x = silu(acc[a][0]); h.y = silu(acc[a][1]);
            h.z = silu(acc[a][2]); h.w = silu(acc[a][3]);
            ((float4*)hs)[(a0 + a) * 32 + fgrp] = h;
        }
    }
    __syncthreads();

    // GEMM2: three 128-wide slices
    for (int s = 0; s < 3; s++) {
        float acc[8][4];
        const float4 bv = *(const float4*)(b2 + s * FDIM + f0);
#pragma unroll
        for (int a = 0; a < 8; a++) {
            acc[a][0] = bv.x; acc[a][1] = bv.y; acc[a][2] = bv.z; acc[a][3] = bv.w;
        }
#pragma unroll 4
        for (int k = 0; k < FDIM; k++) {
            const float4 wv = *(const float4*)(W2 + k * 384 + s * FDIM + f0);
#pragma unroll
            for (int a = 0; a < 8; a++) {
                const float ha = hs[(a0 + a) * FDIM + k];
                acc[a][0] += ha * wv.x; acc[a][1] += ha * wv.y;
                acc[a][2] += ha * wv.z; acc[a][3] += ha * wv.w;
            }
        }
#pragma unroll
        for (int a = 0; a < 8; a++) {
            float4 v = make_float4(acc[a][0], acc[a][1], acc[a][2], acc[a][3]);
            ((float4*)x)[(atom0 + a0 + a) * 96 + s * 32 + fgrp] = v;
        }
    }
}

// ---------------------------------------------------------------------------
// k_pairs: gather x[j], mu[j], desc[p]; scatter RED into dq/dmu.
// One warp per pair iteration, lane = 4 features. 8192 warps, 8 pairs each.
// ---------------------------------------------------------------------------
__global__ void __launch_bounds__(128) k_pairs(
    const float* __restrict__ x, const float* __restrict__ mu,
    const float* __restrict__ desc,
    const float* __restrict__ dist, const float* __restrict__ vec,
    const int* __restrict__ idx_i, const int* __restrict__ idx_j,
    float* __restrict__ dq, float* __restrict__ dmu)
{
    const int lane = threadIdx.x & 31;
    const int gw = blockIdx.x * 4 + (threadIdx.x >> 5);
    const int nw = gridDim.x * 4;
    const float4* D4 = (const float4*)desc;    // [NP][96]
    const float4* X4 = (const float4*)x;       // [NA][96]
    const float4* M4 = (const float4*)mu;      // [NA*3][32]

    for (int p = gw; p < NP; p += nw) {
        const int i = idx_i[p];
        const int j = idx_j[p];
        const float dinv = 1.f / dist[p];
        const float d0 = vec[3 * p] * dinv;
        const float d1 = vec[3 * p + 1] * dinv;
        const float d2 = vec[3 * p + 2] * dinv;

        const float4 wq = D4[p * 96 + lane];
        const float4 wr = D4[p * 96 + 32 + lane];
        const float4 wm = D4[p * 96 + 64 + lane];
        const float4 xq = X4[j * 96 + lane];
        const float4 xr = X4[j * 96 + 32 + lane];
        const float4 xm = X4[j * 96 + 64 + lane];

        red4(dq + i * FDIM + lane * 4,
             xq.x * wq.x, xq.y * wq.y, xq.z * wq.z, xq.w * wq.w);

        const float ax = xr.x * wr.x, ay = xr.y * wr.y, az = xr.z * wr.z, aw = xr.w * wr.w;
        const float cx = xm.x * wm.x, cy = xm.y * wm.y, cz = xm.z * wm.z, cw = xm.w * wm.w;
#pragma unroll
        for (int d = 0; d < 3; d++) {
            const float dd = (d == 0) ? d0 : ((d == 1) ? d1 : d2);
            const float4 mj = M4[(j * 3 + d) * 32 + lane];
            red4(dmu + (i * 3 + d) * FDIM + lane * 4,
                 ax * dd + cx * mj.x,
                 ay * dd + cy * mj.y,
                 az * dd + cz * mj.z,
                 aw * dd + cw * mj.w);
        }
    }
}

// ---------------------------------------------------------------------------
// k_mix: fold deltas, Wv GEMM (mu_V in registers: running norm^2 and V.W dot),
// mixing MLP, gated update. 16 atoms/CTA, 128 threads, 4a x 4f microtile.
// ---------------------------------------------------------------------------
__global__ void __launch_bounds__(128) k_mix(
    float* __restrict__ q, float* __restrict__ mu,
    const float* __restrict__ dq, const float* __restrict__ dmu,
    const float* __restrict__ Wv,                                  // [128][256]
    const float* __restrict__ mW1, const float* __restrict__ mb1,  // [256][128]
    const float* __restrict__ mW2, const float* __restrict__ mb2)  // [128][384]
{
    extern __shared__ float sm[];
    float* qs  = sm;                    // 16*128
    float* mus = qs + 16 * FDIM;        // 16*384
    float* mws = mus + 16 * 384;        // 16*384
    float* ns  = mws + 16 * 384;        // 16*128
    float* hs  = ns + 16 * FDIM;        // 16*128

    const int tid = threadIdx.x;
    const int atom0 = blockIdx.x * 16;
    const int fgrp = tid & 31;
    const int agrp = tid >> 5;          // 4 groups x 4 atoms
    const int f0 = fgrp * 4;
    const int a0 = agrp * 4;

    // fold segment sums into smem
    {
        const float4* src_q = (const float4*)(q + atom0 * FDIM);
        const float4* src_dq = (const float4*)(dq + atom0 * FDIM);
        float4* dst = (float4*)qs;
        for (int c = tid; c < 16 * 32; c += 128) {
            float4 a = src_q[c], b = src_dq[c];
            dst[c] = make_float4(a.x + b.x, a.y + b.y, a.z + b.z, a.w + b.w);
        }
        const float4* src_m = (const float4*)(mu + atom0 * 384);
        const float4* src_dm = (const float4*)(dmu + atom0 * 384);
        float4* dstm = (float4*)mus;
        for (int c = tid; c < 16 * 96; c += 128) {
            float4 a = src_m[c], b = src_dm[c];
            dstm[c] = make_float4(a.x + b.x, a.y + b.y, a.z + b.z, a.w + b.w);
        }
    }
    __syncthreads();

    float dot[4][4], nsq[4][4];
#pragma unroll
    for (int a = 0; a < 4; a++)
#pragma unroll
        for (int c = 0; c < 4; c++) { dot[a][c] = 0.f; nsq[a][c] = 0.f; }

    // [mu_V | mu_W] = mu @ Wv, per spatial dim d
#pragma unroll 1
    for (int d = 0; d < 3; d++) {
        float accV[4][4], accW[4][4];
#pragma unroll
        for (int a = 0; a < 4; a++)
#pragma unroll
            for (int c = 0; c < 4; c++) { accV[a][c] = 0.f; accW[a][c] = 0.f; }
#pragma unroll 4
        for (int k = 0; k < FDIM; k++) {
            const float4 wv = *(const float4*)(Wv + k * 256 + f0);
            const float4 ww = *(const float4*)(Wv + k * 256 + FDIM + f0);
#pragma unroll
            for (int a = 0; a < 4; a++) {
                const float m = mus[(a0 + a) * 384 + d * FDIM + k];
                accV[a][0] += m * wv.x; accV[a][1] += m * wv.y;
                accV[a][2] += m * wv.z; accV[a][3] += m * wv.w;
                accW[a][0] += m * ww.x; accW[a][1] += m * ww.y;
                accW[a][2] += m * ww.z; accW[a][3] += m * ww.w;
            }
        }
#pragma unroll
        for (int a = 0; a < 4; a++) {
            ((float4*)mws)[(a0 + a) * 96 + d * 32 + fgrp] =
                make_float4(accW[a][0], accW[a][1], accW[a][2], accW[a][3]);
#pragma unroll
            for (int c = 0; c < 4; c++) {
                nsq[a][c] += accV[a][c] * accV[a][c];
                dot[a][c] += accV[a][c] * accW[a][c];
            }
        }
    }
#pragma unroll
    for (int a = 0; a < 4; a++)
        ((float4*)ns)[(a0 + a) * 32 + fgrp] =
            make_float4(sqrtf(nsq[a][0] + 1e-8f), sqrtf(nsq[a][1] + 1e-8f),
                        sqrtf(nsq[a][2] + 1e-8f), sqrtf(nsq[a][3] + 1e-8f));
    __syncthreads();

    // h = silu(ctx @ mW1 + mb1), ctx = [q | ||mu_V||]
    {
        float acc[4][4];
        const float4 bv = *(const float4*)(mb1 + f0);
#pragma unroll
        for (int a = 0; a < 4; a++) {
            acc[a][0] = bv.x; acc[a][1] = bv.y; acc[a][2] = bv.z; acc[a][3] = bv.w;
        }
#pragma unroll 4
        for (int k = 0; k < FDIM; k++) {
            const float4 wv = *(const float4*)(mW1 + k * FDIM + f0);
#pragma unroll
            for (int a = 0; a < 4; a++) {
                const float v = qs[(a0 + a) * FDIM + k];
                acc[a][0] += v * wv.x; acc[a][1] += v * wv.y;
                acc[a][2] += v * wv.z; acc[a][3] += v * wv.w;
            }
        }
#pragma unroll 4
        for (int k = 0; k < FDIM; k++) {
            const float4 wv = *(const float4*)(mW1 + (FDIM + k) * FDIM + f0);
#pragma unroll
            for (int a = 0; a < 4; a++) {
                const float v = ns[(a0 + a) * FDIM + k];
                acc[a][0] += v * wv.x; acc[a][1] += v * wv.y;
                acc[a][2] += v * wv.z; acc[a][3] += v * wv.w;
            }
        }
#pragma unroll
        for (int a = 0; a < 4; a++)
            ((float4*)hs)[(a0 + a) * 32 + fgrp] =
                make_float4(silu(acc[a][0]), silu(acc[a][1]),
                            silu(acc[a][2]), silu(acc[a][3]));
    }
    __syncthreads();

    // y = h @ mW2 + mb2 (all 3 slices in one k-pass: 48 FFMA per k per thread)
    {
        float yA[4][4], yB[4][4], yC[4][4];
        const float4 bA = *(const float4*)(mb2 + f0);
        const float4 bB = *(const float4*)(mb2 + FDIM + f0);
        const float4 bC = *(const float4*)(mb2 + 2 * FDIM + f0);
#pragma unroll
        for (int a = 0; a < 4; a++) {
            yA[a][0] = bA.x; yA[a][1] = bA.y; yA[a][2] = bA.z; yA[a][3] = bA.w;
            yB[a][0] = bB.x; yB[a][1] = bB.y; yB[a][2] = bB.z; yB[a][3] = bB.w;
            yC[a][0] = bC.x; yC[a][1] = bC.y; yC[a][2] = bC.z; yC[a][3] = bC.w;
        }
#pragma unroll 2
        for (int k = 0; k < FDIM; k++) {
            const float4 w0 = *(const float4*)(mW2 + k * 384 + f0);
            const float4 w1 = *(const float4*)(mW2 + k * 384 + FDIM + f0);
            const float4 w2 = *(const float4*)(mW2 + k * 384 + 2 * FDIM + f0);
#pragma unroll
            for (int a = 0; a < 4; a++) {
                const float h = hs[(a0 + a) * FDIM + k];
                yA[a][0] += h * w0.x; yA[a][1] += h * w0.y;
                yA[a][2] += h * w0.z; yA[a][3] += h * w0.w;
                yB[a][0] += h * w1.x; yB[a][1] += h * w1.y;
                yB[a][2] += h * w1.z; yB[a][3] += h * w1.w;
                yC[a][0] += h * w2.x; yC[a][1] += h * w2.y;
                yC[a][2] += h * w2.z; yC[a][3] += h * w2.w;
            }
        }
        // gated updates
#pragma unroll
        for (int a = 0; a < 4; a++) {
            const int atom = atom0 + a0 + a;
            const float4 qv = ((const float4*)qs)[(a0 + a) * 32 + fgrp];
            float4 qo;
            qo.x = qv.x + yA[a][0] + yC[a][0] * dot[a][0];
            qo.y = qv.y + yA[a][1] + yC[a][1] * dot[a][1];
            qo.z = qv.z + yA[a][2] + yC[a][2] * dot[a][2];
            qo.w = qv.w + yA[a][3] + yC[a][3] * dot[a][3];
            ((float4*)q)[atom * 32 + fgrp] = qo;
#pragma unroll
            for (int d = 0; d < 3; d++) {
                const float4 mv = ((const float4*)mus)[(a0 + a) * 96 + d * 32 + fgrp];
                const float4 wv = ((const float4*)mws)[(a0 + a) * 96 + d * 32 + fgrp];
                float4 mo;
                mo.x = mv.x + yB[a][0] * wv.x;
                mo.y = mv.y + yB[a][1] * wv.y;
                mo.z = mv.z + yB[a][2] * wv.z;
                mo.w = mv.w + yB[a][3] * wv.w;
                ((float4*)mu)[(atom * 3 + d) * 32 + fgrp] = mo;
            }
        }
    }
}

// ---------------------------------------------------------------------------
extern "C" void kernel_launch(void* const* d_in, const int* in_sizes, int n_in,
                              void* d_out, int out_size)
{
    const float* features = (const float*)d_in[0];
    const float* distances = (const float*)d_in[1];
    const float* vectors = (const float*)d_in[2];
    const float* cutoffs = (const float*)d_in[3];
    const float* rbfs = (const float*)d_in[4];
    const float* filter_W = (const float*)d_in[5];
    const float* filter_b = (const float*)d_in[6];
    const float* int_W1 = (const float*)d_in[7];
    const float* int_b1 = (const float*)d_in[8];
    const float* int_W2 = (const float*)d_in[9];
    const float* int_b2 = (const float*)d_in[10];
    const float* mix_Wv = (const float*)d_in[11];
    const float* mix_W1 = (const float*)d_in[12];
    const float* mix_b1 = (const float*)d_in[13];
    const float* mix_W2 = (const float*)d_in[14];
    const float* mix_b2 = (const float*)d_in[15];
    const int* idx_i = (const int*)d_in[16];
    const int* idx_j = (const int*)d_in[17];

    float* q = (float*)d_out;            // [NA,128]
    float* mu = q + NA * FDIM;           // [NA,3,128]

    float *xbuf, *dqbuf, *dmubuf, *descbuf;
    cudaGetSymbolAddress((void**)&xbuf, g_x);
    cudaGetSymbolAddress((void**)&dqbuf, g_dq);
    cudaGetSymbolAddress((void**)&dmubuf, g_dmu);
    cudaGetSymbolAddress((void**)&descbuf, g_desc);

    const int smem_mix = (16 * FDIM + 16 * 384 * 2 + 16 * FDIM + 16 * FDIM) * 4; // 73728
    cudaFuncSetAttribute(k_mix, cudaFuncAttributeMaxDynamicSharedMemorySize, smem_mix);

    cudaMemcpyAsync(q, features, NA * FDIM * sizeof(float), cudaMemcpyDeviceToDevice);
    cudaMemsetAsync(mu, 0, NA * 384 * sizeof(float));

    for (int b = 0; b < NB; b++) {
        k_filter<<<NP / 32, 384>>>(rbfs, cutoffs,
                                   filter_W + b * 384, filter_b + b * 384,
                                   descbuf);
        k_x<<<NA / 32, 128>>>(q,
                              int_W1 + b * FDIM * FDIM, int_b1 + b * FDIM,
                              int_W2 + b * FDIM * 384, int_b2 + b * 384,
                              xbuf);
        cudaMemsetAsync(dqbuf, 0, NA * FDIM * sizeof(float));
        cudaMemsetAsync(dmubuf, 0, NA * 384 * sizeof(float));
        k_pairs<<<2048, 128>>>(xbuf, mu, descbuf, distances, vectors,
                               idx_i, idx_j, dqbuf, dmubuf);
        k_mix<<<NA / 16, 128, smem_mix>>>(q, mu, dqbuf, dmubuf,
                                          mix_Wv + b * FDIM * 256,
                                          mix_W1 + b * 256 * FDIM, mix_b1 + b * FDIM,
                                          mix_W2 + b * FDIM * 384, mix_b2 + b * 384);
    }
}

// round 5
// speedup vs baseline: 1.6602x; 1.6602x over previous
#include <cuda_runtime.h>
#include <cuda_bf16.h>

#define NA 8192
#define NP 65536
#define FDIM 128
#define RD 20
#define NB 5

typedef unsigned long long ull;

// Scratch (allocation-free rule: __device__ globals)
__device__ __align__(16) float g_x[NA * 384];
__device__ __align__(16) float g_dq[NA * FDIM];
__device__ __align__(16) float g_dmu[NA * 384];

__device__ __forceinline__ float silu(float z) { return z / (1.f + __expf(-z)); }

__device__ __forceinline__ ull pk2(float lo, float hi) {
    ull r; asm("mov.b64 %0,{%1,%2};" : "=l"(r) : "f"(lo), "f"(hi)); return r;
}
__device__ __forceinline__ void upk2(ull v, float& lo, float& hi) {
    asm("mov.b64 {%0,%1},%2;" : "=f"(lo), "=f"(hi) : "l"(v));
}
__device__ __forceinline__ void fma2(ull& acc, ull a, ull b) {
    asm("fma.rn.f32x2 %0,%1,%2,%0;" : "+l"(acc) : "l"(a), "l"(b));
}
__device__ __forceinline__ float hsum(ull v) {
    float lo, hi; upk2(v, lo, hi); return lo + hi;
}

__device__ __forceinline__ void red4(float* p, float a, float b, float c, float d) {
    asm volatile("red.global.add.v4.f32 [%0], {%1,%2,%3,%4};"
                 :: "l"(p), "f"(a), "f"(b), "f"(c), "f"(d) : "memory");
}

// ---------------------------------------------------------------------------
// k_x: x = silu(q @ W1 + b1) @ W2 + b2.  16 atoms/CTA, 128 threads (1 col/thr).
// FFMA2 packed over the k (reduction) dim; activations read as LDS.64 pairs.
// ---------------------------------------------------------------------------
__global__ void __launch_bounds__(128) k_x(
    const float* __restrict__ q,
    const float* __restrict__ W1, const float* __restrict__ b1,
    const float* __restrict__ W2, const float* __restrict__ b2,
    float* __restrict__ x)
{
    __shared__ __align__(16) float qs[16 * FDIM];
    __shared__ __align__(16) float hs[16 * FDIM];
    const int tid = threadIdx.x;
    const int atom0 = blockIdx.x * 16;
    const int f = tid;

    {
        const float4* src = (const float4*)(q + atom0 * FDIM);
        float4* dst = (float4*)qs;
        for (int c = tid; c < 16 * 32; c += 128) dst[c] = src[c];
    }
    __syncthreads();

    const ull* qsu = (const ull*)qs;
    // GEMM1 + silu -> hs
    {
        ull acc[16];
#pragma unroll
        for (int a = 0; a < 16; a++) acc[a] = 0ULL;
#pragma unroll 2
        for (int kp = 0; kp < 64; kp++) {
            const float w0 = W1[(2 * kp) * FDIM + f];
            const float w1 = W1[(2 * kp + 1) * FDIM + f];
            const ull ww = pk2(w0, w1);
#pragma unroll
            for (int a = 0; a < 16; a++) fma2(acc[a], qsu[a * 64 + kp], ww);
        }
        const float bb = b1[f];
#pragma unroll
        for (int a = 0; a < 16; a++) hs[a * FDIM + f] = silu(hsum(acc[a]) + bb);
    }
    __syncthreads();

    // GEMM2: three 128-wide slices
    const ull* hsu = (const ull*)hs;
    for (int s = 0; s < 3; s++) {
        ull acc[16];
#pragma unroll
        for (int a = 0; a < 16; a++) acc[a] = 0ULL;
#pragma unroll 2
        for (int kp = 0; kp < 64; kp++) {
            const float w0 = W2[(2 * kp) * 384 + s * FDIM + f];
            const float w1 = W2[(2 * kp + 1) * 384 + s * FDIM + f];
            const ull ww = pk2(w0, w1);
#pragma unroll
            for (int a = 0; a < 16; a++) fma2(acc[a], hsu[a * 64 + kp], ww);
        }
        const float bb = b2[s * FDIM + f];
#pragma unroll
        for (int a = 0; a < 16; a++)
            x[(atom0 + a) * 384 + s * FDIM + f] = hsum(acc[a]) + bb;
    }
}

// ---------------------------------------------------------------------------
// k_pairs (R1-proven): one warp per pair, lane = 4 features. Filter W_ij
// computed on the fly from rbf and the block's filter slice in smem.
// Scatter via red.global.add.v4.f32 into g_dq / g_dmu.
// ---------------------------------------------------------------------------
__global__ void __launch_bounds__(128) k_pairs(
    const float* __restrict__ x, const float* __restrict__ mu,
    const float* __restrict__ dist, const float* __restrict__ vec,
    const float* __restrict__ cut, const float* __restrict__ rbf,
    const float* __restrict__ fW,   // pre-offset by b*384, row stride 1920
    const float* __restrict__ fb,   // pre-offset by b*384
    const int* __restrict__ idx_i, const int* __restrict__ idx_j,
    float* __restrict__ dq, float* __restrict__ dmu)
{
    __shared__ __align__(16) float fw_s[RD * 384];
    __shared__ __align__(16) float fb_s[384];
    const int tid = threadIdx.x;
    for (int c = tid; c < RD * 384; c += 128) {
        int r = c / 384, cc = c - r * 384;
        fw_s[c] = fW[r * 1920 + cc];
    }
    for (int c = tid; c < 384; c += 128) fb_s[c] = fb[c];
    __syncthreads();

    const int lane = tid & 31;
    const int gw = blockIdx.x * 4 + (tid >> 5);
    const int nw = gridDim.x * 4;
    const float4* fw4 = (const float4*)fw_s;   // [RD][96]
    const float4* fb4 = (const float4*)fb_s;   // [96]
    const float4* X4 = (const float4*)x;       // [NA][96]
    const float4* M4 = (const float4*)mu;      // [NA*3][32]

    for (int p = gw; p < NP; p += nw) {
        const int i = idx_i[p];
        const int j = idx_j[p];
        const float dinv = 1.f / dist[p];
        const float cu = cut[p];
        const float d0 = vec[3 * p] * dinv;
        const float d1 = vec[3 * p + 1] * dinv;
        const float d2 = vec[3 * p + 2] * dinv;

        float4 wq = make_float4(0.f, 0.f, 0.f, 0.f);
        float4 wr = wq, wm = wq;
#pragma unroll
        for (int r = 0; r < RD; r++) {
            float rb = rbf[p * RD + r];
            float4 t;
            t = fw4[r * 96 + lane];
            wq.x += rb * t.x; wq.y += rb * t.y; wq.z += rb * t.z; wq.w += rb * t.w;
            t = fw4[r * 96 + 32 + lane];
            wr.x += rb * t.x; wr.y += rb * t.y; wr.z += rb * t.z; wr.w += rb * t.w;
            t = fw4[r * 96 + 64 + lane];
            wm.x += rb * t.x; wm.y += rb * t.y; wm.z += rb * t.z; wm.w += rb * t.w;
        }
        {
            float4 t = fb4[lane];
            wq.x = (wq.x + t.x) * cu; wq.y = (wq.y + t.y) * cu;
            wq.z = (wq.z + t.z) * cu; wq.w = (wq.w + t.w) * cu;
            t = fb4[32 + lane];
            wr.x = (wr.x + t.x) * cu; wr.y = (wr.y + t.y) * cu;
            wr.z = (wr.z + t.z) * cu; wr.w = (wr.w + t.w) * cu;
            t = fb4[64 + lane];
            wm.x = (wm.x + t.x) * cu; wm.y = (wm.y + t.y) * cu;
            wm.z = (wm.z + t.z) * cu; wm.w = (wm.w + t.w) * cu;
        }
        const float4 xq = X4[j * 96 + lane];
        const float4 xr = X4[j * 96 + 32 + lane];
        const float4 xm = X4[j * 96 + 64 + lane];

        red4(dq + i * FDIM + lane * 4,
             xq.x * wq.x, xq.y * wq.y, xq.z * wq.z, xq.w * wq.w);

        const float ax = xr.x * wr.x, ay = xr.y * wr.y, az = xr.z * wr.z, aw = xr.w * wr.w;
        const float cx = xm.x * wm.x, cy = xm.y * wm.y, cz = xm.z * wm.z, cw = xm.w * wm.w;
#pragma unroll
        for (int d = 0; d < 3; d++) {
            const float dd = (d == 0) ? d0 : ((d == 1) ? d1 : d2);
            const float4 mj = M4[(j * 3 + d) * 32 + lane];
            red4(dmu + (i * 3 + d) * FDIM + lane * 4,
                 ax * dd + cx * mj.x,
                 ay * dd + cy * mj.y,
                 az * dd + cz * mj.z,
                 aw * dd + cw * mj.w);
        }
    }
}

// ---------------------------------------------------------------------------
// k_mix: fold deltas; mu@Wv with running norm^2 and V.W dot in registers;
// mixing MLP; gated update. 8 atoms/CTA, 128 threads (1 col/thr), FFMA2.
// Static smem 36 KB -> ~5 CTAs/SM.
// ---------------------------------------------------------------------------
__global__ void __launch_bounds__(128) k_mix(
    float* __restrict__ q, float* __restrict__ mu,
    const float* __restrict__ dq, const float* __restrict__ dmu,
    const float* __restrict__ Wv,                                  // [128][256]
    const float* __restrict__ mW1, const float* __restrict__ mb1,  // [256][128]
    const float* __restrict__ mW2, const float* __restrict__ mb2)  // [128][384]
{
    __shared__ __align__(16) float qs[8 * FDIM];
    __shared__ __align__(16) float mus[8 * 384];
    __shared__ __align__(16) float mws[8 * 384];
    __shared__ __align__(16) float ns[8 * FDIM];
    __shared__ __align__(16) float hs[8 * FDIM];

    const int tid = threadIdx.x;
    const int atom0 = blockIdx.x * 8;
    const int f = tid;

    // fold segment sums into smem
    {
        const float4* sq = (const float4*)(q + atom0 * FDIM);
        const float4* sdq = (const float4*)(dq + atom0 * FDIM);
        float4* dst = (float4*)qs;
        for (int c = tid; c < 8 * 32; c += 128) {
            float4 a = sq[c], b = sdq[c];
            dst[c] = make_float4(a.x + b.x, a.y + b.y, a.z + b.z, a.w + b.w);
        }
        const float4* sm = (const float4*)(mu + atom0 * 384);
        const float4* sdm = (const float4*)(dmu + atom0 * 384);
        float4* dstm = (float4*)mus;
        for (int c = tid; c < 8 * 96; c += 128) {
            float4 a = sm[c], b = sdm[c];
            dstm[c] = make_float4(a.x + b.x, a.y + b.y, a.z + b.z, a.w + b.w);
        }
    }
    __syncthreads();

    const ull* musu = (const ull*)mus;
    float nsq[8], dot[8];
#pragma unroll
    for (int a = 0; a < 8; a++) { nsq[a] = 0.f; dot[a] = 0.f; }

    // [mu_V | mu_W] = mu @ Wv ; thread f owns V col f and W col 128+f
#pragma unroll 1
    for (int d = 0; d < 3; d++) {
        ull accV[8], accW[8];
#pragma unroll
        for (int a = 0; a < 8; a++) { accV[a] = 0ULL; accW[a] = 0ULL; }
#pragma unroll 2
        for (int kp = 0; kp < 64; kp++) {
            const float v0 = Wv[(2 * kp) * 256 + f];
            const float v1 = Wv[(2 * kp + 1) * 256 + f];
            const float w0 = Wv[(2 * kp) * 256 + FDIM + f];
            const float w1 = Wv[(2 * kp + 1) * 256 + FDIM + f];
            const ull vv = pk2(v0, v1);
            const ull ww = pk2(w0, w1);
#pragma unroll
            for (int a = 0; a < 8; a++) {
                const ull m = musu[a * 192 + d * 64 + kp];
                fma2(accV[a], m, vv);
                fma2(accW[a], m, ww);
            }
        }
#pragma unroll
        for (int a = 0; a < 8; a++) {
            const float v = hsum(accV[a]);
            const float w = hsum(accW[a]);
            mws[a * 384 + d * FDIM + f] = w;
            nsq[a] += v * v;
            dot[a] += v * w;
        }
    }
#pragma unroll
    for (int a = 0; a < 8; a++) ns[a * FDIM + f] = sqrtf(nsq[a] + 1e-8f);
    __syncthreads();

    // h = silu(ctx @ mW1 + mb1), ctx = [q | ||mu_V||]
    {
        const ull* qsu = (const ull*)qs;
        const ull* nsu = (const ull*)ns;
        ull acc[8];
#pragma unroll
        for (int a = 0; a < 8; a++) acc[a] = 0ULL;
#pragma unroll 2
        for (int kp = 0; kp < 64; kp++) {
            const float w0 = mW1[(2 * kp) * FDIM + f];
            const float w1 = mW1[(2 * kp + 1) * FDIM + f];
            const ull ww = pk2(w0, w1);
#pragma unroll
            for (int a = 0; a < 8; a++) fma2(acc[a], qsu[a * 64 + kp], ww);
        }
#pragma unroll 2
        for (int kp = 0; kp < 64; kp++) {
            const float w0 = mW1[(FDIM + 2 * kp) * FDIM + f];
            const float w1 = mW1[(FDIM + 2 * kp + 1) * FDIM + f];
            const ull ww = pk2(w0, w1);
#pragma unroll
            for (int a = 0; a < 8; a++) fma2(acc[a], nsu[a * 64 + kp], ww);
        }
        const float bb = mb1[f];
#pragma unroll
        for (int a = 0; a < 8; a++) hs[a * FDIM + f] = silu(hsum(acc[a]) + bb);
    }
    __syncthreads();

    const ull* hsu = (const ull*)hs;
    // slices A (dq_i) and C (dqmu_i) together -> q update
    {
        ull accA[8], accC[8];
#pragma unroll
        for (int a = 0; a < 8; a++) { accA[a] = 0ULL; accC[a] = 0ULL; }
#pragma unroll 2
        for (int kp = 0; kp < 64; kp++) {
            const float a0 = mW2[(2 * kp) * 384 + f];
            const float a1 = mW2[(2 * kp + 1) * 384 + f];
            const float c0 = mW2[(2 * kp) * 384 + 2 * FDIM + f];
            const float c1 = mW2[(2 * kp + 1) * 384 + 2 * FDIM + f];
            const ull wa = pk2(a0, a1);
            const ull wc = pk2(c0, c1);
#pragma unroll
            for (int a = 0; a < 8; a++) {
                const ull h = hsu[a * 64 + kp];
                fma2(accA[a], h, wa);
                fma2(accC[a], h, wc);
            }
        }
        const float bA = mb2[f], bC = mb2[2 * FDIM + f];
#pragma unroll
        for (int a = 0; a < 8; a++) {
            const float yA = hsum(accA[a]) + bA;
            const float yC = hsum(accC[a]) + bC;
            q[(atom0 + a) * FDIM + f] = qs[a * FDIM + f] + yA + yC * dot[a];
        }
    }
    // slice B (dmu_i) -> mu update
    {
        ull accB[8];
#pragma unroll
        for (int a = 0; a < 8; a++) accB[a] = 0ULL;
#pragma unroll 2
        for (int kp = 0; kp < 64; kp++) {
            const float b0 = mW2[(2 * kp) * 384 + FDIM + f];
            const float b1v = mW2[(2 * kp + 1) * 384 + FDIM + f];
            const ull wb = pk2(b0, b1v);
#pragma unroll
            for (int a = 0; a < 8; a++) fma2(accB[a], hsu[a * 64 + kp], wb);
        }
        const float bB = mb2[FDIM + f];
#pragma unroll
        for (int a = 0; a < 8; a++) {
            const float yB = hsum(accB[a]) + bB;
#pragma unroll
            for (int d = 0; d < 3; d++)
                mu[(atom0 + a) * 384 + d * FDIM + f] =
                    mus[a * 384 + d * FDIM + f] + yB * mws[a * 384 + d * FDIM + f];
        }
    }
}

// ---------------------------------------------------------------------------
extern "C" void kernel_launch(void* const* d_in, const int* in_sizes, int n_in,
                              void* d_out, int out_size)
{
    const float* features = (const float*)d_in[0];
    const float* distances = (const float*)d_in[1];
    const float* vectors = (const float*)d_in[2];
    const float* cutoffs = (const float*)d_in[3];
    const float* rbfs = (const float*)d_in[4];
    const float* filter_W = (const float*)d_in[5];
    const float* filter_b = (const float*)d_in[6];
    const float* int_W1 = (const float*)d_in[7];
    const float* int_b1 = (const float*)d_in[8];
    const float* int_W2 = (const float*)d_in[9];
    const float* int_b2 = (const float*)d_in[10];
    const float* mix_Wv = (const float*)d_in[11];
    const float* mix_W1 = (const float*)d_in[12];
    const float* mix_b1 = (const float*)d_in[13];
    const float* mix_W2 = (const float*)d_in[14];
    const float* mix_b2 = (const float*)d_in[15];
    const int* idx_i = (const int*)d_in[16];
    const int* idx_j = (const int*)d_in[17];

    float* q = (float*)d_out;            // [NA,128]
    float* mu = q + NA * FDIM;           // [NA,3,128]

    float *xbuf, *dqbuf, *dmubuf;
    cudaGetSymbolAddress((void**)&xbuf, g_x);
    cudaGetSymbolAddress((void**)&dqbuf, g_dq);
    cudaGetSymbolAddress((void**)&dmubuf, g_dmu);

    cudaMemcpyAsync(q, features, NA * FDIM * sizeof(float), cudaMemcpyDeviceToDevice);
    cudaMemsetAsync(mu, 0, NA * 384 * sizeof(float));

    for (int b = 0; b < NB; b++) {
        k_x<<<NA / 16, 128>>>(q,
                              int_W1 + b * FDIM * FDIM, int_b1 + b * FDIM,
                              int_W2 + b * FDIM * 384, int_b2 + b * 384,
                              xbuf);
        cudaMemsetAsync(dqbuf, 0, NA * FDIM * sizeof(float));
        cudaMemsetAsync(dmubuf, 0, NA * 384 * sizeof(float));
        k_pairs<<<512, 128>>>(xbuf, mu, distances, vectors, cutoffs, rbfs,
                              filter_W + b * 384, filter_b + b * 384,
                              idx_i, idx_j, dqbuf, dmubuf);
        k_mix<<<NA / 8, 128>>>(q, mu, dqbuf, dmubuf,
                               mix_Wv + b * FDIM * 256,
                               mix_W1 + b * 256 * FDIM, mix_b1 + b * FDIM,
                               mix_W2 + b * FDIM * 384, mix_b2 + b * 384);
    }
}

// round 7
// speedup vs baseline: 2.0596x; 1.2406x over previous
#include <cuda_runtime.h>
#include <cuda_bf16.h>

#define NA 8192
#define NP 65536
#define FDIM 128
#define RD 20
#define NB 5
#define TMX 8

// Scratch (allocation-free rule: __device__ globals)
__device__ __align__(16) float g_x[NA * 384];
__device__ __align__(16) float g_dq[NA * FDIM];
__device__ __align__(16) float g_dmu[NA * 384];

__device__ __forceinline__ float silu(float z) { return z / (1.f + __expf(-z)); }

__device__ __forceinline__ void red4(float* p, float a, float b, float c, float d) {
    asm volatile("red.global.add.v4.f32 [%0], {%1,%2,%3,%4};"
                 :: "l"(p), "f"(a), "f"(b), "f"(c), "f"(d) : "memory");
}

// ---------------------------------------------------------------------------
// k_x: x = silu(q @ W1 + b1) @ W2 + b2.  8 atoms/CTA, 128 threads, 1 col/thr.
// Activation operand: broadcast LDS.128 over 4 k-steps. Weights: scalar LDG.
// ---------------------------------------------------------------------------
__global__ void __launch_bounds__(128) k_x(
    const float* __restrict__ q,
    const float* __restrict__ W1, const float* __restrict__ b1,
    const float* __restrict__ W2, const float* __restrict__ b2,
    float* __restrict__ x)
{
    __shared__ __align__(16) float qs[TMX * FDIM];
    __shared__ __align__(16) float hs[TMX * FDIM];
    const int tid = threadIdx.x;
    const int atom0 = blockIdx.x * TMX;
    const int f = tid;

    {
        const float4* src = (const float4*)(q + atom0 * FDIM);
        float4* dst = (float4*)qs;
        for (int c = tid; c < TMX * 32; c += 128) dst[c] = src[c];
    }
    __syncthreads();

    const float4* qs4 = (const float4*)qs;
    // GEMM1 + silu -> hs
    {
        float acc[TMX];
#pragma unroll
        for (int a = 0; a < TMX; a++) acc[a] = 0.f;
#pragma unroll 2
        for (int kp = 0; kp < 32; kp++) {
            const float w0 = W1[(4 * kp)     * FDIM + f];
            const float w1 = W1[(4 * kp + 1) * FDIM + f];
            const float w2 = W1[(4 * kp + 2) * FDIM + f];
            const float w3 = W1[(4 * kp + 3) * FDIM + f];
#pragma unroll
            for (int a = 0; a < TMX; a++) {
                const float4 v = qs4[a * 32 + kp];
                acc[a] += v.x * w0 + v.y * w1 + v.z * w2 + v.w * w3;
            }
        }
        const float bb = b1[f];
#pragma unroll
        for (int a = 0; a < TMX; a++) hs[a * FDIM + f] = silu(acc[a] + bb);
    }
    __syncthreads();

    // GEMM2: all three 128-wide slices in one k-sweep
    {
        const float4* hs4 = (const float4*)hs;
        float accA[TMX], accB[TMX], accC[TMX];
#pragma unroll
        for (int a = 0; a < TMX; a++) { accA[a] = 0.f; accB[a] = 0.f; accC[a] = 0.f; }
#pragma unroll 2
        for (int kp = 0; kp < 32; kp++) {
            float wa[4], wb[4], wc[4];
#pragma unroll
            for (int t = 0; t < 4; t++) {
                wa[t] = W2[(4 * kp + t) * 384 + f];
                wb[t] = W2[(4 * kp + t) * 384 + FDIM + f];
                wc[t] = W2[(4 * kp + t) * 384 + 2 * FDIM + f];
            }
#pragma unroll
            for (int a = 0; a < TMX; a++) {
                const float4 v = hs4[a * 32 + kp];
                accA[a] += v.x * wa[0] + v.y * wa[1] + v.z * wa[2] + v.w * wa[3];
                accB[a] += v.x * wb[0] + v.y * wb[1] + v.z * wb[2] + v.w * wb[3];
                accC[a] += v.x * wc[0] + v.y * wc[1] + v.z * wc[2] + v.w * wc[3];
            }
        }
        const float bA = b2[f], bB = b2[FDIM + f], bC = b2[2 * FDIM + f];
#pragma unroll
        for (int a = 0; a < TMX; a++) {
            x[(atom0 + a) * 384 + f]            = accA[a] + bA;
            x[(atom0 + a) * 384 + FDIM + f]     = accB[a] + bB;
            x[(atom0 + a) * 384 + 2 * FDIM + f] = accC[a] + bC;
        }
    }
}

// ---------------------------------------------------------------------------
// k_pairs (R1-proven): one warp per pair, lane = 4 features. Filter W_ij
// computed on the fly from rbf and the block's filter slice in smem.
// Scatter via red.global.add.v4.f32 into g_dq / g_dmu.
// ---------------------------------------------------------------------------
__global__ void __launch_bounds__(128) k_pairs(
    const float* __restrict__ x, const float* __restrict__ mu,
    const float* __restrict__ dist, const float* __restrict__ vec,
    const float* __restrict__ cut, const float* __restrict__ rbf,
    const float* __restrict__ fW,   // pre-offset by b*384, row stride 1920
    const float* __restrict__ fb,   // pre-offset by b*384
    const int* __restrict__ idx_i, const int* __restrict__ idx_j,
    float* __restrict__ dq, float* __restrict__ dmu)
{
    __shared__ __align__(16) float fw_s[RD * 384];
    __shared__ __align__(16) float fb_s[384];
    const int tid = threadIdx.x;
    for (int c = tid; c < RD * 384; c += 128) {
        int r = c / 384, cc = c - r * 384;
        fw_s[c] = fW[r * 1920 + cc];
    }
    for (int c = tid; c < 384; c += 128) fb_s[c] = fb[c];
    __syncthreads();

    const int lane = tid & 31;
    const int gw = blockIdx.x * 4 + (tid >> 5);
    const int nw = gridDim.x * 4;
    const float4* fw4 = (const float4*)fw_s;   // [RD][96]
    const float4* fb4 = (const float4*)fb_s;   // [96]
    const float4* X4 = (const float4*)x;       // [NA][96]
    const float4* M4 = (const float4*)mu;      // [NA*3][32]

    for (int p = gw; p < NP; p += nw) {
        const int i = idx_i[p];
        const int j = idx_j[p];
        const float dinv = 1.f / dist[p];
        const float cu = cut[p];
        const float d0 = vec[3 * p] * dinv;
        const float d1 = vec[3 * p + 1] * dinv;
        const float d2 = vec[3 * p + 2] * dinv;

        float4 wq = make_float4(0.f, 0.f, 0.f, 0.f);
        float4 wr = wq, wm = wq;
#pragma unroll
        for (int r = 0; r < RD; r++) {
            float rb = rbf[p * RD + r];
            float4 t;
            t = fw4[r * 96 + lane];
            wq.x += rb * t.x; wq.y += rb * t.y; wq.z += rb * t.z; wq.w += rb * t.w;
            t = fw4[r * 96 + 32 + lane];
            wr.x += rb * t.x; wr.y += rb * t.y; wr.z += rb * t.z; wr.w += rb * t.w;
            t = fw4[r * 96 + 64 + lane];
            wm.x += rb * t.x; wm.y += rb * t.y; wm.z += rb * t.z; wm.w += rb * t.w;
        }
        {
            float4 t = fb4[lane];
            wq.x = (wq.x + t.x) * cu; wq.y = (wq.y + t.y) * cu;
            wq.z = (wq.z + t.z) * cu; wq.w = (wq.w + t.w) * cu;
            t = fb4[32 + lane];
            wr.x = (wr.x + t.x) * cu; wr.y = (wr.y + t.y) * cu;
            wr.z = (wr.z + t.z) * cu; wr.w = (wr.w + t.w) * cu;
            t = fb4[64 + lane];
            wm.x = (wm.x + t.x) * cu; wm.y = (wm.y + t.y) * cu;
            wm.z = (wm.z + t.z) * cu; wm.w = (wm.w + t.w) * cu;
        }
        const float4 xq = X4[j * 96 + lane];
        const float4 xr = X4[j * 96 + 32 + lane];
        const float4 xm = X4[j * 96 + 64 + lane];

        red4(dq + i * FDIM + lane * 4,
             xq.x * wq.x, xq.y * wq.y, xq.z * wq.z, xq.w * wq.w);

        const float ax = xr.x * wr.x, ay = xr.y * wr.y, az = xr.z * wr.z, aw = xr.w * wr.w;
        const float cx = xm.x * wm.x, cy = xm.y * wm.y, cz = xm.z * wm.z, cw = xm.w * wm.w;
#pragma unroll
        for (int d = 0; d < 3; d++) {
            const float dd = (d == 0) ? d0 : ((d == 1) ? d1 : d2);
            const float4 mj = M4[(j * 3 + d) * 32 + lane];
            red4(dmu + (i * 3 + d) * FDIM + lane * 4,
                 ax * dd + cx * mj.x,
                 ay * dd + cy * mj.y,
                 az * dd + cz * mj.z,
                 aw * dd + cw * mj.w);
        }
    }
}

// ---------------------------------------------------------------------------
// k_mix: fold deltas; mu@Wv with running norm^2 and V.W dot in registers;
// mixing MLP; gated update. 8 atoms/CTA, 128 threads, 1 col/thr, scalar FFMA
// with k-vectorized broadcast LDS. Static smem 36 KB.
// ---------------------------------------------------------------------------
__global__ void __launch_bounds__(128) k_mix(
    float* __restrict__ q, float* __restrict__ mu,
    const float* __restrict__ dq, const float* __restrict__ dmu,
    const float* __restrict__ Wv,                                  // [128][256]
    const float* __restrict__ mW1, const float* __restrict__ mb1,  // [256][128]
    const float* __restrict__ mW2, const float* __restrict__ mb2)  // [128][384]
{
    __shared__ __align__(16) float qs[8 * FDIM];
    __shared__ __align__(16) float mus[8 * 384];
    __shared__ __align__(16) float mws[8 * 384];
    __shared__ __align__(16) float ns[8 * FDIM];
    __shared__ __align__(16) float hs[8 * FDIM];

    const int tid = threadIdx.x;
    const int atom0 = blockIdx.x * 8;
    const int f = tid;

    // fold segment sums into smem
    {
        const float4* sq = (const float4*)(q + atom0 * FDIM);
        const float4* sdq = (const float4*)(dq + atom0 * FDIM);
        float4* dst = (float4*)qs;
        for (int c = tid; c < 8 * 32; c += 128) {
            float4 a = sq[c], b = sdq[c];
            dst[c] = make_float4(a.x + b.x, a.y + b.y, a.z + b.z, a.w + b.w);
        }
        const float4* sm = (const float4*)(mu + atom0 * 384);
        const float4* sdm = (const float4*)(dmu + atom0 * 384);
        float4* dstm = (float4*)mus;
        for (int c = tid; c < 8 * 96; c += 128) {
            float4 a = sm[c], b = sdm[c];
            dstm[c] = make_float4(a.x + b.x, a.y + b.y, a.z + b.z, a.w + b.w);
        }
    }
    __syncthreads();

    const float4* mus4 = (const float4*)mus;
    float nsq[8], dot[8];
#pragma unroll
    for (int a = 0; a < 8; a++) { nsq[a] = 0.f; dot[a] = 0.f; }

    // [mu_V | mu_W] = mu @ Wv ; thread f owns V col f and W col 128+f
#pragma unroll 1
    for (int d = 0; d < 3; d++) {
        float accV[8], accW[8];
#pragma unroll
        for (int a = 0; a < 8; a++) { accV[a] = 0.f; accW[a] = 0.f; }
#pragma unroll 2
        for (int kp = 0; kp < 32; kp++) {
            float wv[4], ww[4];
#pragma unroll
            for (int t = 0; t < 4; t++) {
                wv[t] = Wv[(4 * kp + t) * 256 + f];
                ww[t] = Wv[(4 * kp + t) * 256 + FDIM + f];
            }
#pragma unroll
            for (int a = 0; a < 8; a++) {
                const float4 m = mus4[a * 96 + d * 32 + kp];
                accV[a] += m.x * wv[0] + m.y * wv[1] + m.z * wv[2] + m.w * wv[3];
                accW[a] += m.x * ww[0] + m.y * ww[1] + m.z * ww[2] + m.w * ww[3];
            }
        }
#pragma unroll
        for (int a = 0; a < 8; a++) {
            mws[a * 384 + d * FDIM + f] = accW[a];
            nsq[a] += accV[a] * accV[a];
            dot[a] += accV[a] * accW[a];
        }
    }
#pragma unroll
    for (int a = 0; a < 8; a++) ns[a * FDIM + f] = sqrtf(nsq[a] + 1e-8f);
    __syncthreads();

    // h = silu(ctx @ mW1 + mb1), ctx = [q | ||mu_V||]
    {
        const float4* qs4 = (const float4*)qs;
        const float4* ns4 = (const float4*)ns;
        float acc[8];
#pragma unroll
        for (int a = 0; a < 8; a++) acc[a] = 0.f;
#pragma unroll 2
        for (int kp = 0; kp < 32; kp++) {
            float w[4];
#pragma unroll
            for (int t = 0; t < 4; t++) w[t] = mW1[(4 * kp + t) * FDIM + f];
#pragma unroll
            for (int a = 0; a < 8; a++) {
                const float4 v = qs4[a * 32 + kp];
                acc[a] += v.x * w[0] + v.y * w[1] + v.z * w[2] + v.w * w[3];
            }
        }
#pragma unroll 2
        for (int kp = 0; kp < 32; kp++) {
            float w[4];
#pragma unroll
            for (int t = 0; t < 4; t++) w[t] = mW1[(FDIM + 4 * kp + t) * FDIM + f];
#pragma unroll
            for (int a = 0; a < 8; a++) {
                const float4 v = ns4[a * 32 + kp];
                acc[a] += v.x * w[0] + v.y * w[1] + v.z * w[2] + v.w * w[3];
            }
        }
        const float bb = mb1[f];
#pragma unroll
        for (int a = 0; a < 8; a++) hs[a * FDIM + f] = silu(acc[a] + bb);
    }
    __syncthreads();

    // y = h @ mW2 + mb2 (all 3 slices in one k-sweep), then gated updates
    {
        const float4* hs4 = (const float4*)hs;
        float accA[8], accB[8], accC[8];
#pragma unroll
        for (int a = 0; a < 8; a++) { accA[a] = 0.f; accB[a] = 0.f; accC[a] = 0.f; }
#pragma unroll 2
        for (int kp = 0; kp < 32; kp++) {
            float wa[4], wb[4], wc[4];
#pragma unroll
            for (int t = 0; t < 4; t++) {
                wa[t] = mW2[(4 * kp + t) * 384 + f];
                wb[t] = mW2[(4 * kp + t) * 384 + FDIM + f];
                wc[t] = mW2[(4 * kp + t) * 384 + 2 * FDIM + f];
            }
#pragma unroll
            for (int a = 0; a < 8; a++) {
                const float4 v = hs4[a * 32 + kp];
                accA[a] += v.x * wa[0] + v.y * wa[1] + v.z * wa[2] + v.w * wa[3];
                accB[a] += v.x * wb[0] + v.y * wb[1] + v.z * wb[2] + v.w * wb[3];
                accC[a] += v.x * wc[0] + v.y * wc[1] + v.z * wc[2] + v.w * wc[3];
            }
        }
        const float bA = mb2[f], bB = mb2[FDIM + f], bC = mb2[2 * FDIM + f];
#pragma unroll
        for (int a = 0; a < 8; a++) {
            const float yA = accA[a] + bA;
            const float yB = accB[a] + bB;
            const float yC = accC[a] + bC;
            q[(atom0 + a) * FDIM + f] = qs[a * FDIM + f] + yA + yC * dot[a];
#pragma unroll
            for (int d = 0; d < 3; d++)
                mu[(atom0 + a) * 384 + d * FDIM + f] =
                    mus[a * 384 + d * FDIM + f] + yB * mws[a * 384 + d * FDIM + f];
        }
    }
}

// ---------------------------------------------------------------------------
extern "C" void kernel_launch(void* const* d_in, const int* in_sizes, int n_in,
                              void* d_out, int out_size)
{
    const float* features = (const float*)d_in[0];
    const float* distances = (const float*)d_in[1];
    const float* vectors = (const float*)d_in[2];
    const float* cutoffs = (const float*)d_in[3];
    const float* rbfs = (const float*)d_in[4];
    const float* filter_W = (const float*)d_in[5];
    const float* filter_b = (const float*)d_in[6];
    const float* int_W1 = (const float*)d_in[7];
    const float* int_b1 = (const float*)d_in[8];
    const float* int_W2 = (const float*)d_in[9];
    const float* int_b2 = (const float*)d_in[10];
    const float* mix_Wv = (const float*)d_in[11];
    const float* mix_W1 = (const float*)d_in[12];
    const float* mix_b1 = (const float*)d_in[13];
    const float* mix_W2 = (const float*)d_in[14];
    const float* mix_b2 = (const float*)d_in[15];
    const int* idx_i = (const int*)d_in[16];
    const int* idx_j = (const int*)d_in[17];

    float* q = (float*)d_out;            // [NA,128]
    float* mu = q + NA * FDIM;           // [NA,3,128]

    float *xbuf, *dqbuf, *dmubuf;
    cudaGetSymbolAddress((void**)&xbuf, g_x);
    cudaGetSymbolAddress((void**)&dqbuf, g_dq);
    cudaGetSymbolAddress((void**)&dmubuf, g_dmu);

    cudaMemcpyAsync(q, features, NA * FDIM * sizeof(float), cudaMemcpyDeviceToDevice);
    cudaMemsetAsync(mu, 0, NA * 384 * sizeof(float));

    for (int b = 0; b < NB; b++) {
        k_x<<<NA / TMX, 128>>>(q,
                               int_W1 + b * FDIM * FDIM, int_b1 + b * FDIM,
                               int_W2 + b * FDIM * 384, int_b2 + b * 384,
                               xbuf);
        cudaMemsetAsync(dqbuf, 0, NA * FDIM * sizeof(float));
        cudaMemsetAsync(dmubuf, 0, NA * 384 * sizeof(float));
        k_pairs<<<1024, 128>>>(xbuf, mu, distances, vectors, cutoffs, rbfs,
                               filter_W + b * 384, filter_b + b * 384,
                               idx_i, idx_j, dqbuf, dmubuf);
        k_mix<<<NA / 8, 128>>>(q, mu, dqbuf, dmubuf,
                               mix_Wv + b * FDIM * 256,
                               mix_W1 + b * 256 * FDIM, mix_b1 + b * FDIM,
                               mix_W2 + b * FDIM * 384, mix_b2 + b * 384);
    }
}